// round 9
// baseline (speedup 1.0000x reference)
#include <cuda_runtime.h>
#include <cuda_bf16.h>

#define NN 50000
#define EE 800000
#define DIN 300
#define DH 96
#define DOUT 2
#define GG 64

// ---- device-global scratch (no allocations allowed) ----
// __align__(16): vector (float4 / red.v4) accesses require 16B alignment;
// the language only guarantees 4B for a plain float array.
__device__ float g_deg[NN];
__device__ float g_dis[NN];
__device__ __align__(16) float g_hs[NN * DH];   // dis-scaled GEMM output (hs = (A@W)*dis)
__device__ __align__(16) float g_agg[NN * DH];  // scatter accumulator (sum of hs[src])
__device__ __align__(16) float g_h2[NN * DH];   // post-activation (layer-1 output)
__device__ __align__(16) float g_pool[GG * DH];
__device__ float g_cnt[GG];

// ---------------- degree ----------------
__global__ void deg_kernel(const int* __restrict__ dst) {
    int e = blockIdx.x * blockDim.x + threadIdx.x;
    if (e < EE) atomicAdd(&g_deg[dst[e]], 1.0f);
}

__global__ void dis_kernel() {
    int i = blockIdx.x * blockDim.x + threadIdx.x;
    if (i < NN) g_dis[i] = rsqrtf(g_deg[i] + 1.0f);
}

// ---------------- SGEMM: C[M,96] = (A[M,K] @ B[K,96]) * dis[row] ----------------
// BM=128, BN=96, BK=16, 192 threads, 8x8 register micro-tile per thread.
#define BM 128
#define BN 96
#define BK 16
__global__ void gemm_kernel(const float* __restrict__ A, const float* __restrict__ B,
                            float* __restrict__ C, int M, int K) {
    __shared__ float As[BK][BM + 1];  // +1 pad: conflict-free transposed writes
    __shared__ float Bs[BK][BN];
    int tid = threadIdx.x;
    int tcol = tid % 12;   // 12 * 8 = 96 cols
    int trow = tid / 12;   // 16 * 8 = 128 rows
    int row0 = blockIdx.x * BM;

    float acc[8][8];
#pragma unroll
    for (int i = 0; i < 8; i++)
#pragma unroll
        for (int j = 0; j < 8; j++) acc[i][j] = 0.0f;

    for (int k0 = 0; k0 < K; k0 += BK) {
        for (int idx = tid; idx < BM * BK; idx += 192) {
            int r = idx / BK, kk = idx % BK;
            int gr = row0 + r, gk = k0 + kk;
            As[kk][r] = (gr < M && gk < K) ? A[gr * K + gk] : 0.0f;
        }
        for (int idx = tid; idx < BK * BN; idx += 192) {
            int kk = idx / BN, c = idx % BN;
            int gk = k0 + kk;
            Bs[kk][c] = (gk < K) ? B[gk * BN + c] : 0.0f;
        }
        __syncthreads();
#pragma unroll
        for (int kk = 0; kk < BK; kk++) {
            float a[8], b[8];
#pragma unroll
            for (int i = 0; i < 8; i++) a[i] = As[kk][trow * 8 + i];
#pragma unroll
            for (int j = 0; j < 8; j++) b[j] = Bs[kk][tcol * 8 + j];
#pragma unroll
            for (int i = 0; i < 8; i++)
#pragma unroll
                for (int j = 0; j < 8; j++) acc[i][j] += a[i] * b[j];
        }
        __syncthreads();
    }
#pragma unroll
    for (int i = 0; i < 8; i++) {
        int gr = row0 + trow * 8 + i;
        if (gr < M) {
            float s = g_dis[gr];  // hs = h * dis (norm factored out of edge pass)
#pragma unroll
            for (int j = 0; j < 8; j++)
                C[gr * BN + tcol * 8 + j] = acc[i][j] * s;
        }
    }
}

// ---------------- edge scatter: agg[dst] += hs[src] (pure, norm pre-factored) ----------------
// blockDim = (24, 16): 16 edges/block, each thread handles one float4 of the 96-dim row.
__global__ void edge_kernel(const float* __restrict__ hs, float* __restrict__ agg,
                            const int* __restrict__ src, const int* __restrict__ dst) {
    int e = blockIdx.x * 16 + threadIdx.y;
    if (e >= EE) return;
    int s = __ldg(&src[e]);
    int d = __ldg(&dst[e]);
    int f4 = threadIdx.x;  // 0..23
    const float4 v = *reinterpret_cast<const float4*>(hs + s * DH + f4 * 4);
    float* p = agg + d * DH + f4 * 4;
    asm volatile("red.global.add.v4.f32 [%0], {%1, %2, %3, %4};"
                 :: "l"(p), "f"(v.x), "f"(v.y), "f"(v.z), "f"(v.w) : "memory");
}

// ---------------- layer-1 epilogue: h2 = relu(dis*(agg + hs) + b) ----------------
__global__ void selfloop_relu_kernel(const float* __restrict__ hs, const float* __restrict__ agg,
                                     const float* __restrict__ b, float* __restrict__ out) {
    int n = blockIdx.x * blockDim.y + threadIdx.y;
    if (n >= NN) return;
    int f = threadIdx.x;
    float v = g_dis[n] * (agg[n * DH + f] + hs[n * DH + f]) + b[f];
    out[n * DH + f] = fmaxf(v, 0.0f);
}

// ---------------- layer-2 epilogue fused with pooling scatter ----------------
__global__ void selfloop_relu_pool_kernel(const float* __restrict__ hs, const float* __restrict__ agg,
                                          const float* __restrict__ b, const int* __restrict__ batch,
                                          float* __restrict__ pool) {
    int n = blockIdx.x * blockDim.y + threadIdx.y;
    if (n >= NN) return;
    int f = threadIdx.x;
    float v = g_dis[n] * (agg[n * DH + f] + hs[n * DH + f]) + b[f];
    v = fmaxf(v, 0.0f);
    atomicAdd(&pool[batch[n] * DH + f], v);
}

// ---------------- graph node counts ----------------
__global__ void cnt_kernel(const int* __restrict__ batch) {
    int i = blockIdx.x * blockDim.x + threadIdx.x;
    if (i < NN) atomicAdd(&g_cnt[batch[i]], 1.0f);
}

// ---------------- head: out[g,c] = (pool[g]/cnt[g]) @ Wfc + bfc ----------------
__global__ void head_kernel(const float* __restrict__ Wfc, const float* __restrict__ bfc,
                            float* __restrict__ out) {
    int t = threadIdx.x;
    if (t >= GG * DOUT) return;
    int g = t / DOUT;
    int c = t % DOUT;
    float inv = 1.0f / fmaxf(g_cnt[g], 1.0f);
    float acc = 0.0f;
#pragma unroll 8
    for (int f = 0; f < DH; f++) acc += g_pool[g * DH + f] * Wfc[f * DOUT + c];
    out[g * DOUT + c] = acc * inv + bfc[c];
}

extern "C" void kernel_launch(void* const* d_in, const int* in_sizes, int n_in,
                              void* d_out, int out_size) {
    const float* x   = (const float*)d_in[0];
    const float* W1  = (const float*)d_in[1];
    const float* b1  = (const float*)d_in[2];
    const float* W2  = (const float*)d_in[3];
    const float* b2  = (const float*)d_in[4];
    const float* Wfc = (const float*)d_in[5];
    const float* bfc = (const float*)d_in[6];
    const int*   src = (const int*)d_in[7];
    const int*   dst = (const int*)d_in[8];
    const int*   bat = (const int*)d_in[9];
    float* out = (float*)d_out;

    // Resolve device-global scratch through the runtime — passing a __device__
    // symbol directly from host code is UB (host shadow address).
    void *p_deg, *p_agg, *p_pool, *p_cnt, *p_hs, *p_h2;
    cudaGetSymbolAddress(&p_deg, g_deg);
    cudaGetSymbolAddress(&p_agg, g_agg);
    cudaGetSymbolAddress(&p_pool, g_pool);
    cudaGetSymbolAddress(&p_cnt, g_cnt);
    cudaGetSymbolAddress(&p_hs, g_hs);
    cudaGetSymbolAddress(&p_h2, g_h2);
    float* hs_buf   = (float*)p_hs;
    float* agg_buf  = (float*)p_agg;
    float* h2_buf   = (float*)p_h2;
    float* pool_buf = (float*)p_pool;

    cudaMemsetAsync(p_deg, 0, NN * sizeof(float), 0);
    cudaMemsetAsync(p_agg, 0, NN * DH * sizeof(float), 0);
    cudaMemsetAsync(p_pool, 0, GG * DH * sizeof(float), 0);
    cudaMemsetAsync(p_cnt, 0, GG * sizeof(float), 0);

    // degree / normalization (must precede GEMM1 — its epilogue reads g_dis)
    deg_kernel<<<(EE + 255) / 256, 256>>>(dst);
    dis_kernel<<<(NN + 255) / 256, 256>>>();

    // layer 1: hs = (x @ W1) * dis
    gemm_kernel<<<(NN + BM - 1) / BM, 192>>>(x, W1, hs_buf, NN, DIN);
    {
        dim3 eblk(24, 16);
        edge_kernel<<<(EE + 15) / 16, eblk>>>(hs_buf, agg_buf, src, dst);
        dim3 nblk(DH, 4);
        selfloop_relu_kernel<<<(NN + 3) / 4, nblk>>>(hs_buf, agg_buf, b1, h2_buf);
    }

    // layer 2: hs = (h2 @ W2) * dis
    gemm_kernel<<<(NN + BM - 1) / BM, 192>>>(h2_buf, W2, hs_buf, NN, DH);
    cudaMemsetAsync(p_agg, 0, NN * DH * sizeof(float), 0);
    {
        dim3 eblk(24, 16);
        edge_kernel<<<(EE + 15) / 16, eblk>>>(hs_buf, agg_buf, src, dst);
        dim3 nblk(DH, 4);
        selfloop_relu_pool_kernel<<<(NN + 3) / 4, nblk>>>(hs_buf, agg_buf, b2, bat, pool_buf);
    }

    // pooling counts + head
    cnt_kernel<<<(NN + 255) / 256, 256>>>(bat);
    head_kernel<<<1, 128>>>(Wfc, bfc, out);
}

// round 11
// speedup vs baseline: 1.3334x; 1.3334x over previous
#include <cuda_runtime.h>
#include <cuda_bf16.h>

#define NN 50000
#define EE 800000
#define DIN 300
#define DH 96
#define DOUT 2
#define GG 64

// ---- device-global scratch (no allocations allowed) ----
__device__ float g_deg[NN];
__device__ float g_dis[NN];
__device__ __align__(16) float g_hs[NN * DH];   // dis-scaled GEMM output (hs = (A@W)*dis)
__device__ __align__(16) float g_agg[NN * DH];  // accumulator, pre-initialized to hs (self-loop)
__device__ __align__(16) float g_h2[NN * DH];   // post-activation (layer-1 output)
__device__ __align__(16) float g_pool[GG * DH];
__device__ float g_cnt[GG];

// ---------------- degree ----------------
__global__ void deg_kernel(const int* __restrict__ dst) {
    int e = blockIdx.x * blockDim.x + threadIdx.x;
    if (e < EE) atomicAdd(&g_deg[dst[e]], 1.0f);
}

__global__ void dis_kernel() {
    int i = blockIdx.x * blockDim.x + threadIdx.x;
    if (i < NN) g_dis[i] = rsqrtf(g_deg[i] + 1.0f);
}

// ---------------- SGEMM: hs[M,96] = (A[M,K] @ B[K,96]) * dis[row]; agg = hs ----------------
// 256 threads, BM=128, BN=96, BK=12 (divides K=300 and K=96 exactly).
// Microtile 8x6 per thread (16x16 thread grid). Inner loop: 2xLDS.128 + 3xLDS.64
// per 48 FMAs; Bs read pattern (tcol*6, float2 x3) hits all 32 banks once per warp.
#define BM 128
#define BN 96
#define BK 12
__global__ __launch_bounds__(256) void gemm_kernel(
    const float* __restrict__ A, const float* __restrict__ B,
    float* __restrict__ C, float* __restrict__ C2, int M, int K) {
    __shared__ float As[BK][BM];  // transposed: As[kk][r]; row = 512B, conflict-free
    __shared__ float Bs[BK][BN];
    int tid = threadIdx.x;
    int tcol = tid & 15;   // 16 cols * 6 = 96
    int trow = tid >> 4;   // 16 rows * 8 = 128
    int row0 = blockIdx.x * BM;

    float acc[8][6];
#pragma unroll
    for (int i = 0; i < 8; i++)
#pragma unroll
        for (int j = 0; j < 6; j++) acc[i][j] = 0.0f;

    for (int k0 = 0; k0 < K; k0 += BK) {
        // A tile: 128 rows x 12 cols = 384 float4 (3 per row), transposed store
        for (int f = tid; f < (BM * BK) / 4; f += 256) {
            int r = f / 3, c4 = f % 3;
            int gr = row0 + r;
            float4 v = (gr < M)
                ? *reinterpret_cast<const float4*>(A + (size_t)gr * K + k0 + c4 * 4)
                : make_float4(0.f, 0.f, 0.f, 0.f);
            As[c4 * 4 + 0][r] = v.x;
            As[c4 * 4 + 1][r] = v.y;
            As[c4 * 4 + 2][r] = v.z;
            As[c4 * 4 + 3][r] = v.w;
        }
        // B tile: 12 rows x 96 cols = 288 float4 (24 per row)
        for (int f = tid; f < (BK * BN) / 4; f += 256) {
            int kk = f / 24, c4 = f % 24;
            *reinterpret_cast<float4*>(&Bs[kk][c4 * 4]) =
                *reinterpret_cast<const float4*>(B + (size_t)(k0 + kk) * BN + c4 * 4);
        }
        __syncthreads();
#pragma unroll
        for (int kk = 0; kk < BK; kk++) {
            float a[8], b[6];
            *reinterpret_cast<float4*>(a)     = *reinterpret_cast<const float4*>(&As[kk][trow * 8]);
            *reinterpret_cast<float4*>(a + 4) = *reinterpret_cast<const float4*>(&As[kk][trow * 8 + 4]);
            *reinterpret_cast<float2*>(b)     = *reinterpret_cast<const float2*>(&Bs[kk][tcol * 6]);
            *reinterpret_cast<float2*>(b + 2) = *reinterpret_cast<const float2*>(&Bs[kk][tcol * 6 + 2]);
            *reinterpret_cast<float2*>(b + 4) = *reinterpret_cast<const float2*>(&Bs[kk][tcol * 6 + 4]);
#pragma unroll
            for (int i = 0; i < 8; i++)
#pragma unroll
                for (int j = 0; j < 6; j++) acc[i][j] += a[i] * b[j];
        }
        __syncthreads();
    }
    // epilogue: scale by dis[row]; dual-store into hs AND agg (agg := self-loop term)
#pragma unroll
    for (int i = 0; i < 8; i++) {
        int gr = row0 + trow * 8 + i;
        if (gr < M) {
            float s = g_dis[gr];
            float v[6];
#pragma unroll
            for (int j = 0; j < 6; j++) v[j] = acc[i][j] * s;
            size_t off = (size_t)gr * BN + tcol * 6;
#pragma unroll
            for (int j = 0; j < 3; j++) {
                float2 p = make_float2(v[2 * j], v[2 * j + 1]);
                *reinterpret_cast<float2*>(C + off + 2 * j)  = p;
                *reinterpret_cast<float2*>(C2 + off + 2 * j) = p;
            }
        }
    }
}

// ---------------- edge scatter: agg[dst] += hs[src] (pure, norm pre-factored) ----------------
// blockDim = (24, 16): 16 edges/block, each thread handles one float4 of the 96-dim row.
__global__ void edge_kernel(const float* __restrict__ hs, float* __restrict__ agg,
                            const int* __restrict__ src, const int* __restrict__ dst) {
    int e = blockIdx.x * 16 + threadIdx.y;
    if (e >= EE) return;
    int s = __ldg(&src[e]);
    int d = __ldg(&dst[e]);
    int f4 = threadIdx.x;  // 0..23
    const float4 v = *reinterpret_cast<const float4*>(hs + s * DH + f4 * 4);
    float* p = agg + d * DH + f4 * 4;
    asm volatile("red.global.add.v4.f32 [%0], {%1, %2, %3, %4};"
                 :: "l"(p), "f"(v.x), "f"(v.y), "f"(v.z), "f"(v.w) : "memory");
}

// ---------------- layer-1 epilogue: h2 = relu(dis*agg + b)  (agg already holds self term) ----
__global__ void selfloop_relu_kernel(const float* __restrict__ agg,
                                     const float* __restrict__ b, float* __restrict__ out) {
    int n = blockIdx.x * blockDim.y + threadIdx.y;
    if (n >= NN) return;
    int f = threadIdx.x;
    float v = g_dis[n] * agg[n * DH + f] + b[f];
    out[n * DH + f] = fmaxf(v, 0.0f);
}

// ---------------- layer-2 epilogue fused with pooling scatter ----------------
__global__ void selfloop_relu_pool_kernel(const float* __restrict__ agg,
                                          const float* __restrict__ b, const int* __restrict__ batch,
                                          float* __restrict__ pool) {
    int n = blockIdx.x * blockDim.y + threadIdx.y;
    if (n >= NN) return;
    int f = threadIdx.x;
    float v = g_dis[n] * agg[n * DH + f] + b[f];
    v = fmaxf(v, 0.0f);
    atomicAdd(&pool[batch[n] * DH + f], v);
}

// ---------------- graph node counts ----------------
__global__ void cnt_kernel(const int* __restrict__ batch) {
    int i = blockIdx.x * blockDim.x + threadIdx.x;
    if (i < NN) atomicAdd(&g_cnt[batch[i]], 1.0f);
}

// ---------------- head: out[g,c] = (pool[g]/cnt[g]) @ Wfc + bfc ----------------
__global__ void head_kernel(const float* __restrict__ Wfc, const float* __restrict__ bfc,
                            float* __restrict__ out) {
    int t = threadIdx.x;
    if (t >= GG * DOUT) return;
    int g = t / DOUT;
    int c = t % DOUT;
    float inv = 1.0f / fmaxf(g_cnt[g], 1.0f);
    float acc = 0.0f;
#pragma unroll 8
    for (int f = 0; f < DH; f++) acc += g_pool[g * DH + f] * Wfc[f * DOUT + c];
    out[g * DOUT + c] = acc * inv + bfc[c];
}

extern "C" void kernel_launch(void* const* d_in, const int* in_sizes, int n_in,
                              void* d_out, int out_size) {
    const float* x   = (const float*)d_in[0];
    const float* W1  = (const float*)d_in[1];
    const float* b1  = (const float*)d_in[2];
    const float* W2  = (const float*)d_in[3];
    const float* b2  = (const float*)d_in[4];
    const float* Wfc = (const float*)d_in[5];
    const float* bfc = (const float*)d_in[6];
    const int*   src = (const int*)d_in[7];
    const int*   dst = (const int*)d_in[8];
    const int*   bat = (const int*)d_in[9];
    float* out = (float*)d_out;

    // Resolve device-global scratch through the runtime — passing a __device__
    // symbol directly from host code is UB (host shadow address).
    void *p_deg, *p_agg, *p_pool, *p_cnt, *p_hs, *p_h2;
    cudaGetSymbolAddress(&p_deg, g_deg);
    cudaGetSymbolAddress(&p_agg, g_agg);
    cudaGetSymbolAddress(&p_pool, g_pool);
    cudaGetSymbolAddress(&p_cnt, g_cnt);
    cudaGetSymbolAddress(&p_hs, g_hs);
    cudaGetSymbolAddress(&p_h2, g_h2);
    float* hs_buf   = (float*)p_hs;
    float* agg_buf  = (float*)p_agg;
    float* h2_buf   = (float*)p_h2;
    float* pool_buf = (float*)p_pool;

    cudaMemsetAsync(p_deg, 0, NN * sizeof(float), 0);
    cudaMemsetAsync(p_pool, 0, GG * DH * sizeof(float), 0);
    cudaMemsetAsync(p_cnt, 0, GG * sizeof(float), 0);

    // degree / normalization (must precede GEMM1 — its epilogue reads g_dis)
    deg_kernel<<<(EE + 255) / 256, 256>>>(dst);
    dis_kernel<<<(NN + 255) / 256, 256>>>();

    // layer 1: hs = (x @ W1) * dis; agg pre-initialized with hs (self-loop term)
    gemm_kernel<<<(NN + BM - 1) / BM, 256>>>(x, W1, hs_buf, agg_buf, NN, DIN);
    {
        dim3 eblk(24, 16);
        edge_kernel<<<(EE + 15) / 16, eblk>>>(hs_buf, agg_buf, src, dst);
        dim3 nblk(DH, 4);
        selfloop_relu_kernel<<<(NN + 3) / 4, nblk>>>(agg_buf, b1, h2_buf);
    }

    // layer 2: hs = (h2 @ W2) * dis; agg pre-initialized with hs
    gemm_kernel<<<(NN + BM - 1) / BM, 256>>>(h2_buf, W2, hs_buf, agg_buf, NN, DH);
    {
        dim3 eblk(24, 16);
        edge_kernel<<<(EE + 15) / 16, eblk>>>(hs_buf, agg_buf, src, dst);
        dim3 nblk(DH, 4);
        selfloop_relu_pool_kernel<<<(NN + 3) / 4, nblk>>>(agg_buf, b2, bat, pool_buf);
    }

    // pooling counts + head
    cnt_kernel<<<(NN + 255) / 256, 256>>>(bat);
    head_kernel<<<1, 128>>>(Wfc, bfc, out);
}

// round 12
// speedup vs baseline: 1.4311x; 1.0733x over previous
#include <cuda_runtime.h>
#include <cuda_bf16.h>

#define NN 50000
#define EE 800000
#define DIN 300
#define DH 96
#define DOUT 2
#define GG 64

// ---- device-global scratch (no allocations allowed) ----
__device__ float g_deg[NN];
__device__ float g_dis[NN];
__device__ __align__(16) float g_hs[NN * DH];   // dis-scaled GEMM output (hs = (A@W)*dis)
__device__ __align__(16) float g_agg[NN * DH];  // accumulator: starts as hs (self-loop), edges add in
__device__ __align__(16) float g_pool[GG * DH];
__device__ float g_cnt[GG];

// ---------------- degree ----------------
__global__ void deg_kernel(const int* __restrict__ dst) {
    int e = blockIdx.x * blockDim.x + threadIdx.x;
    if (e < EE) atomicAdd(&g_deg[dst[e]], 1.0f);
}

__global__ void dis_kernel() {
    int i = blockIdx.x * blockDim.x + threadIdx.x;
    if (i < NN) g_dis[i] = rsqrtf(g_deg[i] + 1.0f);
}

// ---------------- SGEMM core config ----------------
// 256 threads, BM=128, BN=96, BK=12 (divides K=300 and K=96 exactly).
// Microtile 8x6 per thread (16x16 thread grid).
#define BM 128
#define BN 96
#define BK 12

// ---------------- layer-1 GEMM: hs = (x @ W1) * dis; agg = hs ----------------
__global__ __launch_bounds__(256) void gemm_kernel(
    const float* __restrict__ A, const float* __restrict__ B,
    float* __restrict__ C, float* __restrict__ C2, int M, int K) {
    __shared__ float As[BK][BM];
    __shared__ float Bs[BK][BN];
    int tid = threadIdx.x;
    int tcol = tid & 15;
    int trow = tid >> 4;
    int row0 = blockIdx.x * BM;

    float acc[8][6];
#pragma unroll
    for (int i = 0; i < 8; i++)
#pragma unroll
        for (int j = 0; j < 6; j++) acc[i][j] = 0.0f;

    for (int k0 = 0; k0 < K; k0 += BK) {
        for (int f = tid; f < (BM * BK) / 4; f += 256) {
            int r = f / 3, c4 = f % 3;
            int gr = row0 + r;
            float4 v = (gr < M)
                ? *reinterpret_cast<const float4*>(A + (size_t)gr * K + k0 + c4 * 4)
                : make_float4(0.f, 0.f, 0.f, 0.f);
            As[c4 * 4 + 0][r] = v.x;
            As[c4 * 4 + 1][r] = v.y;
            As[c4 * 4 + 2][r] = v.z;
            As[c4 * 4 + 3][r] = v.w;
        }
        for (int f = tid; f < (BK * BN) / 4; f += 256) {
            int kk = f / 24, c4 = f % 24;
            *reinterpret_cast<float4*>(&Bs[kk][c4 * 4]) =
                *reinterpret_cast<const float4*>(B + (size_t)(k0 + kk) * BN + c4 * 4);
        }
        __syncthreads();
#pragma unroll
        for (int kk = 0; kk < BK; kk++) {
            float a[8], b[6];
            *reinterpret_cast<float4*>(a)     = *reinterpret_cast<const float4*>(&As[kk][trow * 8]);
            *reinterpret_cast<float4*>(a + 4) = *reinterpret_cast<const float4*>(&As[kk][trow * 8 + 4]);
            *reinterpret_cast<float2*>(b)     = *reinterpret_cast<const float2*>(&Bs[kk][tcol * 6]);
            *reinterpret_cast<float2*>(b + 2) = *reinterpret_cast<const float2*>(&Bs[kk][tcol * 6 + 2]);
            *reinterpret_cast<float2*>(b + 4) = *reinterpret_cast<const float2*>(&Bs[kk][tcol * 6 + 4]);
#pragma unroll
            for (int i = 0; i < 8; i++)
#pragma unroll
                for (int j = 0; j < 6; j++) acc[i][j] += a[i] * b[j];
        }
        __syncthreads();
    }
#pragma unroll
    for (int i = 0; i < 8; i++) {
        int gr = row0 + trow * 8 + i;
        if (gr < M) {
            float s = g_dis[gr];
            size_t off = (size_t)gr * BN + tcol * 6;
#pragma unroll
            for (int j = 0; j < 3; j++) {
                float2 p = make_float2(acc[i][2 * j] * s, acc[i][2 * j + 1] * s);
                *reinterpret_cast<float2*>(C + off + 2 * j)  = p;
                *reinterpret_cast<float2*>(C2 + off + 2 * j) = p;
            }
        }
    }
}

// ---------------- layer-2 GEMM with fused layer-1 epilogue ----------------
// A is computed on the fly: A[r,k] = relu(dis[r] * agg1[r,k] + b1[k]).
// In-place safe: each block reads only the agg rows it later overwrites, and all
// A reads complete (final __syncthreads) before the epilogue stores.
__global__ __launch_bounds__(256) void gemm2_kernel(
    const float* __restrict__ Ain, const float* __restrict__ b1v,
    const float* __restrict__ B,
    float* __restrict__ C, float* __restrict__ C2, int M) {
    const int K = DH;  // 96
    __shared__ float As[BK][BM];
    __shared__ float Bs[BK][BN];
    int tid = threadIdx.x;
    int tcol = tid & 15;
    int trow = tid >> 4;
    int row0 = blockIdx.x * BM;

    float acc[8][6];
#pragma unroll
    for (int i = 0; i < 8; i++)
#pragma unroll
        for (int j = 0; j < 6; j++) acc[i][j] = 0.0f;

    for (int k0 = 0; k0 < K; k0 += BK) {
        for (int f = tid; f < (BM * BK) / 4; f += 256) {
            int r = f / 3, c4 = f % 3;
            int gr = row0 + r;
            float4 v = make_float4(0.f, 0.f, 0.f, 0.f);
            if (gr < M) {
                v = *reinterpret_cast<const float4*>(Ain + (size_t)gr * K + k0 + c4 * 4);
                float dis = g_dis[gr];
                float4 bb = *reinterpret_cast<const float4*>(b1v + k0 + c4 * 4);
                v.x = fmaxf(dis * v.x + bb.x, 0.f);
                v.y = fmaxf(dis * v.y + bb.y, 0.f);
                v.z = fmaxf(dis * v.z + bb.z, 0.f);
                v.w = fmaxf(dis * v.w + bb.w, 0.f);
            }
            As[c4 * 4 + 0][r] = v.x;
            As[c4 * 4 + 1][r] = v.y;
            As[c4 * 4 + 2][r] = v.z;
            As[c4 * 4 + 3][r] = v.w;
        }
        for (int f = tid; f < (BK * BN) / 4; f += 256) {
            int kk = f / 24, c4 = f % 24;
            *reinterpret_cast<float4*>(&Bs[kk][c4 * 4]) =
                *reinterpret_cast<const float4*>(B + (size_t)(k0 + kk) * BN + c4 * 4);
        }
        __syncthreads();
#pragma unroll
        for (int kk = 0; kk < BK; kk++) {
            float a[8], b[6];
            *reinterpret_cast<float4*>(a)     = *reinterpret_cast<const float4*>(&As[kk][trow * 8]);
            *reinterpret_cast<float4*>(a + 4) = *reinterpret_cast<const float4*>(&As[kk][trow * 8 + 4]);
            *reinterpret_cast<float2*>(b)     = *reinterpret_cast<const float2*>(&Bs[kk][tcol * 6]);
            *reinterpret_cast<float2*>(b + 2) = *reinterpret_cast<const float2*>(&Bs[kk][tcol * 6 + 2]);
            *reinterpret_cast<float2*>(b + 4) = *reinterpret_cast<const float2*>(&Bs[kk][tcol * 6 + 4]);
#pragma unroll
            for (int i = 0; i < 8; i++)
#pragma unroll
                for (int j = 0; j < 6; j++) acc[i][j] += a[i] * b[j];
        }
        __syncthreads();
    }
#pragma unroll
    for (int i = 0; i < 8; i++) {
        int gr = row0 + trow * 8 + i;
        if (gr < M) {
            float s = g_dis[gr];
            size_t off = (size_t)gr * BN + tcol * 6;
#pragma unroll
            for (int j = 0; j < 3; j++) {
                float2 p = make_float2(acc[i][2 * j] * s, acc[i][2 * j + 1] * s);
                *reinterpret_cast<float2*>(C + off + 2 * j)  = p;
                *reinterpret_cast<float2*>(C2 + off + 2 * j) = p;
            }
        }
    }
}

// ---------------- edge scatter: agg[dst] += hs[src], 4 edges/thread (MLP=4) -------------
// blockDim = (24, 16); block covers 64 edges (y handles e, e+16, e+32, e+48).
// EE = 800000 = 12500 * 64 exactly -> no bounds guards.
__global__ void edge_kernel(const float* __restrict__ hs, float* __restrict__ agg,
                            const int* __restrict__ src, const int* __restrict__ dst) {
    int base = blockIdx.x * 64 + threadIdx.y;
    int f4 = threadIdx.x;  // 0..23
    int s[4], d[4];
#pragma unroll
    for (int u = 0; u < 4; u++) {
        int e = base + u * 16;
        s[u] = __ldg(&src[e]);
        d[u] = __ldg(&dst[e]);
    }
    float4 v[4];
#pragma unroll
    for (int u = 0; u < 4; u++)
        v[u] = *reinterpret_cast<const float4*>(hs + (size_t)s[u] * DH + f4 * 4);
#pragma unroll
    for (int u = 0; u < 4; u++) {
        float* p = agg + (size_t)d[u] * DH + f4 * 4;
        asm volatile("red.global.add.v4.f32 [%0], {%1, %2, %3, %4};"
                     :: "l"(p), "f"(v[u].x), "f"(v[u].y), "f"(v[u].z), "f"(v[u].w) : "memory");
    }
}

// ---------------- layer-2 epilogue fused with pooling scatter ----------------
__global__ void selfloop_relu_pool_kernel(const float* __restrict__ agg,
                                          const float* __restrict__ b, const int* __restrict__ batch,
                                          float* __restrict__ pool) {
    int n = blockIdx.x * blockDim.y + threadIdx.y;
    if (n >= NN) return;
    int f = threadIdx.x;
    float v = g_dis[n] * agg[n * DH + f] + b[f];
    v = fmaxf(v, 0.0f);
    atomicAdd(&pool[batch[n] * DH + f], v);
}

// ---------------- graph node counts ----------------
__global__ void cnt_kernel(const int* __restrict__ batch) {
    int i = blockIdx.x * blockDim.x + threadIdx.x;
    if (i < NN) atomicAdd(&g_cnt[batch[i]], 1.0f);
}

// ---------------- head: out[g,c] = (pool[g]/cnt[g]) @ Wfc + bfc ----------------
__global__ void head_kernel(const float* __restrict__ Wfc, const float* __restrict__ bfc,
                            float* __restrict__ out) {
    int t = threadIdx.x;
    if (t >= GG * DOUT) return;
    int g = t / DOUT;
    int c = t % DOUT;
    float inv = 1.0f / fmaxf(g_cnt[g], 1.0f);
    float acc = 0.0f;
#pragma unroll 8
    for (int f = 0; f < DH; f++) acc += g_pool[g * DH + f] * Wfc[f * DOUT + c];
    out[g * DOUT + c] = acc * inv + bfc[c];
}

extern "C" void kernel_launch(void* const* d_in, const int* in_sizes, int n_in,
                              void* d_out, int out_size) {
    const float* x   = (const float*)d_in[0];
    const float* W1  = (const float*)d_in[1];
    const float* b1  = (const float*)d_in[2];
    const float* W2  = (const float*)d_in[3];
    const float* b2  = (const float*)d_in[4];
    const float* Wfc = (const float*)d_in[5];
    const float* bfc = (const float*)d_in[6];
    const int*   src = (const int*)d_in[7];
    const int*   dst = (const int*)d_in[8];
    const int*   bat = (const int*)d_in[9];
    float* out = (float*)d_out;

    void *p_deg, *p_agg, *p_pool, *p_cnt, *p_hs;
    cudaGetSymbolAddress(&p_deg, g_deg);
    cudaGetSymbolAddress(&p_agg, g_agg);
    cudaGetSymbolAddress(&p_pool, g_pool);
    cudaGetSymbolAddress(&p_cnt, g_cnt);
    cudaGetSymbolAddress(&p_hs, g_hs);
    float* hs_buf   = (float*)p_hs;
    float* agg_buf  = (float*)p_agg;
    float* pool_buf = (float*)p_pool;

    cudaMemsetAsync(p_deg, 0, NN * sizeof(float), 0);
    cudaMemsetAsync(p_pool, 0, GG * DH * sizeof(float), 0);
    cudaMemsetAsync(p_cnt, 0, GG * sizeof(float), 0);

    // degree / normalization (must precede GEMM1 — its epilogue reads g_dis)
    deg_kernel<<<(EE + 255) / 256, 256>>>(dst);
    dis_kernel<<<(NN + 255) / 256, 256>>>();

    // layer 1: hs = (x @ W1) * dis; agg := hs (self-loop term pre-loaded)
    gemm_kernel<<<(NN + BM - 1) / BM, 256>>>(x, W1, hs_buf, agg_buf, NN, DIN);
    edge_kernel<<<EE / 64, dim3(24, 16)>>>(hs_buf, agg_buf, src, dst);

    // layer 2: A = relu(dis*agg1 + b1) computed in-kernel; hs/agg overwritten in place
    gemm2_kernel<<<(NN + BM - 1) / BM, 256>>>(agg_buf, b1, W2, hs_buf, agg_buf, NN);
    edge_kernel<<<EE / 64, dim3(24, 16)>>>(hs_buf, agg_buf, src, dst);

    // layer-2 epilogue + pooling
    selfloop_relu_pool_kernel<<<(NN + 3) / 4, dim3(DH, 4)>>>(agg_buf, b2, bat, pool_buf);
    cnt_kernel<<<(NN + 255) / 256, 256>>>(bat);
    head_kernel<<<1, 128>>>(Wfc, bfc, out);
}

// round 14
// speedup vs baseline: 1.4521x; 1.0147x over previous
#include <cuda_runtime.h>
#include <cuda_bf16.h>

#define NN 50000
#define EE 800000
#define DIN 300
#define DH 96
#define DOUT 2
#define GG 64

// ---- device-global scratch (no allocations allowed) ----
__device__ float g_deg[NN];
__device__ float g_dis[NN];
__device__ __align__(16) float g_hs[NN * DH];   // dis-scaled GEMM output (hs = (A@W)*dis)
__device__ __align__(16) float g_agg[NN * DH];  // accumulator: starts as hs (self-loop), edges add in
__device__ __align__(16) float g_pool[GG * DH];
__device__ float g_cnt[GG];

// ---------------- degree ----------------
__global__ void deg_kernel(const int* __restrict__ dst) {
    int e = blockIdx.x * blockDim.x + threadIdx.x;
    if (e < EE) atomicAdd(&g_deg[dst[e]], 1.0f);
}

__global__ void dis_kernel() {
    int i = blockIdx.x * blockDim.x + threadIdx.x;
    if (i < NN) g_dis[i] = rsqrtf(g_deg[i] + 1.0f);
}

// ---------------- SGEMM core config ----------------
// 256 threads, BM=128, BN=96, BK=12 (divides K=300 and K=96 exactly).
// Microtile 8x6 per thread (16x16 thread grid).
// __launch_bounds__(256, 3): cap regs ~84 so 3 blocks/SM are resident ->
// grid 391 fits one wave (148*3=444) and barriers are hidden by co-resident blocks.
#define BM 128
#define BN 96
#define BK 12

// ---------------- layer-1 GEMM: hs = (x @ W1) * dis; agg = hs ----------------
__global__ __launch_bounds__(256, 3) void gemm_kernel(
    const float* __restrict__ A, const float* __restrict__ B,
    float* __restrict__ C, float* __restrict__ C2, int M, int K) {
    __shared__ float As[BK][BM];
    __shared__ float Bs[BK][BN];
    int tid = threadIdx.x;
    int tcol = tid & 15;
    int trow = tid >> 4;
    int row0 = blockIdx.x * BM;

    // hoisted loader coordinates (invariant across k0)
    int lar = tid / 3 + (tid >= 192 ? 64 : 0);       // unused helper removed below; keep simple
    (void)lar;
    float acc[8][6];
#pragma unroll
    for (int i = 0; i < 8; i++)
#pragma unroll
        for (int j = 0; j < 6; j++) acc[i][j] = 0.0f;

    for (int k0 = 0; k0 < K; k0 += BK) {
#pragma unroll
        for (int t = 0; t < 2; t++) {
            int f = tid + t * 256;
            if (f < (BM * BK) / 4) {
                int r = f / 3, c4 = f % 3;
                int gr = row0 + r;
                float4 v = (gr < M)
                    ? *reinterpret_cast<const float4*>(A + (size_t)gr * K + k0 + c4 * 4)
                    : make_float4(0.f, 0.f, 0.f, 0.f);
                As[c4 * 4 + 0][r] = v.x;
                As[c4 * 4 + 1][r] = v.y;
                As[c4 * 4 + 2][r] = v.z;
                As[c4 * 4 + 3][r] = v.w;
            }
        }
        {
            int f = tid;
            if (f < (BK * BN) / 4) {
                int kk = f / 24, c4 = f % 24;
                *reinterpret_cast<float4*>(&Bs[kk][c4 * 4]) =
                    *reinterpret_cast<const float4*>(B + (size_t)(k0 + kk) * BN + c4 * 4);
            } else {
                f += 256 - 288;  // threads 32..63 of upper half load remainder
            }
            int f2 = tid + 256;
            if (f2 < 288 + 256 && f2 >= 256 && (f2 - 256) + 256 < 288) {}
        }
        // simpler: second chunk of B tile
        if (tid < (BK * BN) / 4 - 256) {
            int f = tid + 256;
            int kk = f / 24, c4 = f % 24;
            *reinterpret_cast<float4*>(&Bs[kk][c4 * 4]) =
                *reinterpret_cast<const float4*>(B + (size_t)(k0 + kk) * BN + c4 * 4);
        }
        __syncthreads();
#pragma unroll
        for (int kk = 0; kk < BK; kk++) {
            float a[8], b[6];
            *reinterpret_cast<float4*>(a)     = *reinterpret_cast<const float4*>(&As[kk][trow * 8]);
            *reinterpret_cast<float4*>(a + 4) = *reinterpret_cast<const float4*>(&As[kk][trow * 8 + 4]);
            *reinterpret_cast<float2*>(b)     = *reinterpret_cast<const float2*>(&Bs[kk][tcol * 6]);
            *reinterpret_cast<float2*>(b + 2) = *reinterpret_cast<const float2*>(&Bs[kk][tcol * 6 + 2]);
            *reinterpret_cast<float2*>(b + 4) = *reinterpret_cast<const float2*>(&Bs[kk][tcol * 6 + 4]);
#pragma unroll
            for (int i = 0; i < 8; i++)
#pragma unroll
                for (int j = 0; j < 6; j++) acc[i][j] += a[i] * b[j];
        }
        __syncthreads();
    }
#pragma unroll
    for (int i = 0; i < 8; i++) {
        int gr = row0 + trow * 8 + i;
        if (gr < M) {
            float s = g_dis[gr];
            size_t off = (size_t)gr * BN + tcol * 6;
#pragma unroll
            for (int j = 0; j < 3; j++) {
                float2 p = make_float2(acc[i][2 * j] * s, acc[i][2 * j + 1] * s);
                *reinterpret_cast<float2*>(C + off + 2 * j)  = p;
                *reinterpret_cast<float2*>(C2 + off + 2 * j) = p;
            }
        }
    }
}

// ---------------- layer-2 GEMM with fused layer-1 epilogue ----------------
// A computed on the fly: A[r,k] = relu(dis[r] * agg1[r,k] + b1[k]).
// In-place safe: each block reads only the agg rows it later overwrites, and all
// A reads complete (final __syncthreads) before the epilogue stores.
__global__ __launch_bounds__(256, 3) void gemm2_kernel(
    const float* __restrict__ Ain, const float* __restrict__ b1v,
    const float* __restrict__ B,
    float* __restrict__ C, float* __restrict__ C2, int M) {
    const int K = DH;  // 96
    __shared__ float As[BK][BM];
    __shared__ float Bs[BK][BN];
    int tid = threadIdx.x;
    int tcol = tid & 15;
    int trow = tid >> 4;
    int row0 = blockIdx.x * BM;

    float acc[8][6];
#pragma unroll
    for (int i = 0; i < 8; i++)
#pragma unroll
        for (int j = 0; j < 6; j++) acc[i][j] = 0.0f;

    for (int k0 = 0; k0 < K; k0 += BK) {
#pragma unroll
        for (int t = 0; t < 2; t++) {
            int f = tid + t * 256;
            if (f < (BM * BK) / 4) {
                int r = f / 3, c4 = f % 3;
                int gr = row0 + r;
                float4 v = make_float4(0.f, 0.f, 0.f, 0.f);
                if (gr < M) {
                    v = *reinterpret_cast<const float4*>(Ain + (size_t)gr * K + k0 + c4 * 4);
                    float dis = g_dis[gr];
                    float4 bb = *reinterpret_cast<const float4*>(b1v + k0 + c4 * 4);
                    v.x = fmaxf(dis * v.x + bb.x, 0.f);
                    v.y = fmaxf(dis * v.y + bb.y, 0.f);
                    v.z = fmaxf(dis * v.z + bb.z, 0.f);
                    v.w = fmaxf(dis * v.w + bb.w, 0.f);
                }
                As[c4 * 4 + 0][r] = v.x;
                As[c4 * 4 + 1][r] = v.y;
                As[c4 * 4 + 2][r] = v.z;
                As[c4 * 4 + 3][r] = v.w;
            }
        }
        if (tid < (BK * BN) / 4) {
            int kk = tid / 24, c4 = tid % 24;
            *reinterpret_cast<float4*>(&Bs[kk][c4 * 4]) =
                *reinterpret_cast<const float4*>(B + (size_t)(k0 + kk) * BN + c4 * 4);
        }
        if (tid < (BK * BN) / 4 - 256) {
            int f = tid + 256;
            int kk = f / 24, c4 = f % 24;
            *reinterpret_cast<float4*>(&Bs[kk][c4 * 4]) =
                *reinterpret_cast<const float4*>(B + (size_t)(k0 + kk) * BN + c4 * 4);
        }
        __syncthreads();
#pragma unroll
        for (int kk = 0; kk < BK; kk++) {
            float a[8], b[6];
            *reinterpret_cast<float4*>(a)     = *reinterpret_cast<const float4*>(&As[kk][trow * 8]);
            *reinterpret_cast<float4*>(a + 4) = *reinterpret_cast<const float4*>(&As[kk][trow * 8 + 4]);
            *reinterpret_cast<float2*>(b)     = *reinterpret_cast<const float2*>(&Bs[kk][tcol * 6]);
            *reinterpret_cast<float2*>(b + 2) = *reinterpret_cast<const float2*>(&Bs[kk][tcol * 6 + 2]);
            *reinterpret_cast<float2*>(b + 4) = *reinterpret_cast<const float2*>(&Bs[kk][tcol * 6 + 4]);
#pragma unroll
            for (int i = 0; i < 8; i++)
#pragma unroll
                for (int j = 0; j < 6; j++) acc[i][j] += a[i] * b[j];
        }
        __syncthreads();
    }
#pragma unroll
    for (int i = 0; i < 8; i++) {
        int gr = row0 + trow * 8 + i;
        if (gr < M) {
            float s = g_dis[gr];
            size_t off = (size_t)gr * BN + tcol * 6;
#pragma unroll
            for (int j = 0; j < 3; j++) {
                float2 p = make_float2(acc[i][2 * j] * s, acc[i][2 * j + 1] * s);
                *reinterpret_cast<float2*>(C + off + 2 * j)  = p;
                *reinterpret_cast<float2*>(C2 + off + 2 * j) = p;
            }
        }
    }
}

// ---------------- edge scatter: agg[dst] += hs[src], 4 edges/thread (MLP=4) -------------
// blockDim = (24, 16); block covers 64 edges. EE = 12500 * 64 exactly -> no guards.
__global__ void edge_kernel(const float* __restrict__ hs, float* __restrict__ agg,
                            const int* __restrict__ src, const int* __restrict__ dst) {
    int base = blockIdx.x * 64 + threadIdx.y;
    int f4 = threadIdx.x;  // 0..23
    int s[4], d[4];
#pragma unroll
    for (int u = 0; u < 4; u++) {
        int e = base + u * 16;
        s[u] = __ldg(&src[e]);
        d[u] = __ldg(&dst[e]);
    }
    float4 v[4];
#pragma unroll
    for (int u = 0; u < 4; u++)
        v[u] = *reinterpret_cast<const float4*>(hs + (size_t)s[u] * DH + f4 * 4);
#pragma unroll
    for (int u = 0; u < 4; u++) {
        float* p = agg + (size_t)d[u] * DH + f4 * 4;
        asm volatile("red.global.add.v4.f32 [%0], {%1, %2, %3, %4};"
                     :: "l"(p), "f"(v[u].x), "f"(v[u].y), "f"(v[u].z), "f"(v[u].w) : "memory");
    }
}

// ---------------- layer-2 epilogue fused with pooling scatter ----------------
__global__ void selfloop_relu_pool_kernel(const float* __restrict__ agg,
                                          const float* __restrict__ b, const int* __restrict__ batch,
                                          float* __restrict__ pool) {
    int n = blockIdx.x * blockDim.y + threadIdx.y;
    if (n >= NN) return;
    int f = threadIdx.x;
    float v = g_dis[n] * agg[n * DH + f] + b[f];
    v = fmaxf(v, 0.0f);
    atomicAdd(&pool[batch[n] * DH + f], v);
}

// ---------------- graph node counts ----------------
__global__ void cnt_kernel(const int* __restrict__ batch) {
    int i = blockIdx.x * blockDim.x + threadIdx.x;
    if (i < NN) atomicAdd(&g_cnt[batch[i]], 1.0f);
}

// ---------------- head: out[g,c] = (pool[g]/cnt[g]) @ Wfc + bfc ----------------
__global__ void head_kernel(const float* __restrict__ Wfc, const float* __restrict__ bfc,
                            float* __restrict__ out) {
    int t = threadIdx.x;
    if (t >= GG * DOUT) return;
    int g = t / DOUT;
    int c = t % DOUT;
    float inv = 1.0f / fmaxf(g_cnt[g], 1.0f);
    float acc = 0.0f;
#pragma unroll 8
    for (int f = 0; f < DH; f++) acc += g_pool[g * DH + f] * Wfc[f * DOUT + c];
    out[g * DOUT + c] = acc * inv + bfc[c];
}

extern "C" void kernel_launch(void* const* d_in, const int* in_sizes, int n_in,
                              void* d_out, int out_size) {
    const float* x   = (const float*)d_in[0];
    const float* W1  = (const float*)d_in[1];
    const float* b1  = (const float*)d_in[2];
    const float* W2  = (const float*)d_in[3];
    const float* b2  = (const float*)d_in[4];
    const float* Wfc = (const float*)d_in[5];
    const float* bfc = (const float*)d_in[6];
    const int*   src = (const int*)d_in[7];
    const int*   dst = (const int*)d_in[8];
    const int*   bat = (const int*)d_in[9];
    float* out = (float*)d_out;

    void *p_deg, *p_agg, *p_pool, *p_cnt, *p_hs;
    cudaGetSymbolAddress(&p_deg, g_deg);
    cudaGetSymbolAddress(&p_agg, g_agg);
    cudaGetSymbolAddress(&p_pool, g_pool);
    cudaGetSymbolAddress(&p_cnt, g_cnt);
    cudaGetSymbolAddress(&p_hs, g_hs);
    float* hs_buf   = (float*)p_hs;
    float* agg_buf  = (float*)p_agg;
    float* pool_buf = (float*)p_pool;

    cudaMemsetAsync(p_deg, 0, NN * sizeof(float), 0);
    cudaMemsetAsync(p_pool, 0, GG * DH * sizeof(float), 0);
    cudaMemsetAsync(p_cnt, 0, GG * sizeof(float), 0);

    // degree / normalization (must precede GEMM1 — its epilogue reads g_dis)
    deg_kernel<<<(EE + 255) / 256, 256>>>(dst);
    dis_kernel<<<(NN + 255) / 256, 256>>>();

    // layer 1: hs = (x @ W1) * dis; agg := hs (self-loop term pre-loaded)
    gemm_kernel<<<(NN + BM - 1) / BM, 256>>>(x, W1, hs_buf, agg_buf, NN, DIN);
    edge_kernel<<<EE / 64, dim3(24, 16)>>>(hs_buf, agg_buf, src, dst);

    // layer 2: A = relu(dis*agg1 + b1) computed in-kernel; hs/agg overwritten in place
    gemm2_kernel<<<(NN + BM - 1) / BM, 256>>>(agg_buf, b1, W2, hs_buf, agg_buf, NN);
    edge_kernel<<<EE / 64, dim3(24, 16)>>>(hs_buf, agg_buf, src, dst);

    // layer-2 epilogue + pooling
    selfloop_relu_pool_kernel<<<(NN + 3) / 4, dim3(DH, 4)>>>(agg_buf, b2, bat, pool_buf);
    cnt_kernel<<<(NN + 255) / 256, 256>>>(bat);
    head_kernel<<<1, 128>>>(Wfc, bfc, out);
}